// round 13
// baseline (speedup 1.0000x reference)
#include <cuda_runtime.h>
#include <stdint.h>

typedef unsigned long long ull;

#define KBOX 256
#define CCH  512
#define NTOK 1024
#define HH   32
#define OSZ  7
#define KDIM (CCH * OSZ * OSZ)          // 25088
#define BM   64
#define BN   64
#define BKC  16
#define SPLITK 8
#define KSPLIT (KDIM / SPLITK)          // 3136
#define KITER  (KSPLIT / BKC)           // 196

// f32 round-to-nearest of 1/7 (0x3E124925) — XLA rewrites x/7 to x*(1/7)
#define RECIP7 0.14285715f

// Scratch (static __device__ arrays: allocation-free per harness rules)
__device__ __align__(16) float g_pool[(size_t)KBOX * KDIM];           // 25.7 MB
__device__ __align__(16) float g_part[(size_t)SPLITK * KBOX * CCH];   // 4.2 MB

// ---- f32x2 packed-FMA helpers (differentially validated vs scalar SGEMM) ----
__device__ __forceinline__ ull dup2(float v) {
    ull d; asm("mov.b64 %0, {%1, %1};" : "=l"(d) : "f"(v)); return d;
}
__device__ __forceinline__ ull fma2(ull a, ull b, ull c) {
    ull d; asm("fma.rn.f32x2 %0, %1, %2, %3;" : "=l"(d) : "l"(a), "l"(b), "l"(c)); return d;
}
__device__ __forceinline__ void unpack2(ull v, float& lo, float& hi) {
    asm("mov.b64 {%0, %1}, %2;" : "=f"(lo), "=f"(hi) : "l"(v));
}

// ============================================================================
// Stage 1: ROI max pool. One block per box, one thread per channel.
// KEY FIX: bin_sz = roi * rn(1/7)  (multiply-by-reciprocal), matching XLA's
// constant-division canonicalization — NOT IEEE div.rn(roi, 7). The ~1-ulp
// difference flips floor/ceil bin edges at near-integer products and was the
// sole source of the bit-stable rel_err = 0.199 across R4/R6/R10.
// ============================================================================
__global__ void pool_kernel(const float* __restrict__ x,
                            const float* __restrict__ boxes) {
    const int k = blockIdx.x;
    const int c = threadIdx.x;

    const int   b  = (int)boxes[k * 5 + 0];
    const float x1 = rintf(boxes[k * 5 + 1] * 32.0f);   // *32 exact (2^5)
    const float y1 = rintf(boxes[k * 5 + 2] * 32.0f);
    const float x2 = rintf(boxes[k * 5 + 3] * 32.0f);
    const float y2 = rintf(boxes[k * 5 + 4] * 32.0f);
    const float rw = fmaxf(x2 - x1 + 1.0f, 1.0f);
    const float rh = fmaxf(y2 - y1 + 1.0f, 1.0f);
    const float bw = __fmul_rn(rw, RECIP7);   // reciprocal-multiply, like XLA
    const float bh = __fmul_rn(rh, RECIP7);

    int xlo[OSZ], xhi[OSZ], ylo[OSZ], yhi[OSZ];
#pragma unroll
    for (int p = 0; p < OSZ; p++) {
        float pf = (float)p;
        float lo = floorf(__fmul_rn(pf, bw)) + x1;
        float hi = ceilf(__fmul_rn(pf + 1.0f, bw)) + x1;
        lo = fminf(fmaxf(lo, 0.0f), 32.0f);
        hi = fminf(fmaxf(hi, 0.0f), 32.0f);
        xlo[p] = (int)lo; xhi[p] = (int)hi;
        lo = floorf(__fmul_rn(pf, bh)) + y1;
        hi = ceilf(__fmul_rn(pf + 1.0f, bh)) + y1;
        lo = fminf(fmaxf(lo, 0.0f), 32.0f);
        hi = fminf(fmaxf(hi, 0.0f), 32.0f);
        ylo[p] = (int)lo; yhi[p] = (int)hi;
    }

    // feat[b,c,h,w] = x[b, h*32+w, c]
    const float* xb   = x + (size_t)b * NTOK * CCH + c;
    float*       outp = g_pool + (size_t)k * KDIM + (size_t)c * (OSZ * OSZ);

    for (int i = 0; i < OSZ; i++) {          // i = row bin (y/h)
        const int h0 = ylo[i], h1 = yhi[i];
        for (int j = 0; j < OSZ; j++) {      // j = col bin (x/w)
            const int w0 = xlo[j], w1 = xhi[j];
            float m = -3.402823466e38f;
            for (int h = h0; h < h1; h++) {
                const float* row = xb + (size_t)(h * HH) * CCH;
                for (int w = w0; w < w1; w++)
                    m = fmaxf(m, row[(size_t)w * CCH]);
            }
            if (h1 <= h0 || w1 <= w0) m = 0.0f;   // empty bin -> 0
            outp[i * OSZ + j] = m;
        }
    }
}

// ============================================================================
// Stage 2: split-K GEMM  part[s] = pool(256 x Ks) * conv_w^T(Ks x 512)
// 64x64 tiles, BK=16, 256 threads, 4x4 micro-tile via packed f32x2 FMA.
// Bit-validated against the canonical scalar SGEMM in R4/R6.
// ============================================================================
__global__ __launch_bounds__(256) void gemm_kernel(const float* __restrict__ conv_w) {
    __shared__ ull   As2[BKC][BM + 1];   // duplicated (a,a) pairs
    __shared__ float Bs[BKC][BN + 4];    // row = 272B keeps 16B alignment

    const int tid  = threadIdx.x;
    const int n0   = blockIdx.x * BN;
    const int m0   = blockIdx.y * BM;
    const int s    = blockIdx.z;
    const int kbeg = s * KSPLIT;

    const int lrow = tid >> 2;          // 0..63
    const int lk4  = (tid & 3) * 4;     // 0,4,8,12
    const int ty4  = (tid >> 4) * 4;    // 0..60
    const int tx4  = (tid & 15) * 4;    // 0..60

    const float* Ag = g_pool + (size_t)(m0 + lrow) * KDIM + kbeg + lk4;
    const float* Bg = conv_w + (size_t)(n0 + lrow) * KDIM + kbeg + lk4;

    ull acc00 = 0, acc01 = 0, acc10 = 0, acc11 = 0;
    ull acc20 = 0, acc21 = 0, acc30 = 0, acc31 = 0;

    for (int kt = 0; kt < KITER; kt++) {
        const float4 av = *(const float4*)Ag;
        const float4 bv = *(const float4*)Bg;
        Ag += BKC; Bg += BKC;

        __syncthreads();
        As2[lk4 + 0][lrow] = dup2(av.x);
        As2[lk4 + 1][lrow] = dup2(av.y);
        As2[lk4 + 2][lrow] = dup2(av.z);
        As2[lk4 + 3][lrow] = dup2(av.w);
        Bs[lk4 + 0][lrow] = bv.x;
        Bs[lk4 + 1][lrow] = bv.y;
        Bs[lk4 + 2][lrow] = bv.z;
        Bs[lk4 + 3][lrow] = bv.w;
        __syncthreads();

#pragma unroll
        for (int kk = 0; kk < BKC; kk++) {
            const ull a0 = As2[kk][ty4 + 0];
            const ull a1 = As2[kk][ty4 + 1];
            const ull a2 = As2[kk][ty4 + 2];
            const ull a3 = As2[kk][ty4 + 3];
            const ull* bp = (const ull*)&Bs[kk][tx4];
            const ull b01 = bp[0];
            const ull b23 = bp[1];
            acc00 = fma2(a0, b01, acc00); acc01 = fma2(a0, b23, acc01);
            acc10 = fma2(a1, b01, acc10); acc11 = fma2(a1, b23, acc11);
            acc20 = fma2(a2, b01, acc20); acc21 = fma2(a2, b23, acc21);
            acc30 = fma2(a3, b01, acc30); acc31 = fma2(a3, b23, acc31);
        }
    }

    float* P = g_part + (size_t)s * KBOX * CCH;
    ull ar0[4] = {acc00, acc10, acc20, acc30};
    ull ar1[4] = {acc01, acc11, acc21, acc31};
#pragma unroll
    for (int r = 0; r < 4; r++) {
        float4 v;
        unpack2(ar0[r], v.x, v.y);
        unpack2(ar1[r], v.z, v.w);
        *(float4*)&P[(size_t)(m0 + ty4 + r) * CCH + n0 + tx4] = v;
    }
}

// ============================================================================
// Stage 3: reduce split-K partials + bias -> out (256 x 512), deterministic.
// ============================================================================
__global__ void reduce_kernel(const float* __restrict__ bias,
                              float* __restrict__ out) {
    const int idx = blockIdx.x * blockDim.x + threadIdx.x;
    if (idx >= KBOX * CCH) return;
    float sum = bias[idx & (CCH - 1)];
#pragma unroll
    for (int p = 0; p < SPLITK; p++)
        sum += g_part[(size_t)p * KBOX * CCH + idx];
    out[idx] = sum;
}

extern "C" void kernel_launch(void* const* d_in, const int* in_sizes, int n_in,
                              void* d_out, int out_size) {
    // Select inputs by element count (robust to metadata ordering):
    // x=4194304, boxes=1280, box_labels=256, conv_w=12845056, conv_b=512
    const float* x      = nullptr;
    const float* boxes  = nullptr;
    const float* conv_w = nullptr;
    const float* conv_b = nullptr;
    for (int i = 0; i < n_in; i++) {
        switch (in_sizes[i]) {
            case 4194304:  x      = (const float*)d_in[i]; break;
            case 1280:     boxes  = (const float*)d_in[i]; break;
            case 12845056: conv_w = (const float*)d_in[i]; break;
            case 512:      conv_b = (const float*)d_in[i]; break;
            default: break;                    // box_labels (256): unused
        }
    }
    float* out = (float*)d_out;
    const size_t NX = 4194304;

    // Output layout: (x passthrough, box_feats)
    cudaMemcpyAsync(out, x, NX * sizeof(float), cudaMemcpyDeviceToDevice, 0);

    pool_kernel<<<KBOX, CCH>>>(x, boxes);

    dim3 grid(CCH / BN, KBOX / BM, SPLITK);   // (8, 4, 8) = 256 CTAs
    gemm_kernel<<<grid, 256>>>(conv_w);

    reduce_kernel<<<(KBOX * CCH + 255) / 256, 256>>>(conv_b, out + NX);
}

// round 16
// speedup vs baseline: 1.2176x; 1.2176x over previous
#include <cuda_runtime.h>
#include <stdint.h>

typedef unsigned long long ull;

#define KBOX 256
#define CCH  512
#define NTOK 1024
#define HH   32
#define OSZ  7
#define KDIM (CCH * OSZ * OSZ)          // 25088
#define BM   128
#define BN   128
#define BK   8
#define SPLITK 32
#define KSPLIT (KDIM / SPLITK)          // 784
#define KITER  (KSPLIT / BK)            // 98

// f32 round-to-nearest of 1/7 (0x3E124925) — XLA rewrites x/7 to x*(1/7)
#define RECIP7 0.14285715f
#define NEGINF (-3.402823466e38f)

// Scratch (static __device__ arrays: allocation-free per harness rules)
__device__ __align__(16) float g_pool[(size_t)KBOX * KDIM];           // 25.7 MB
__device__ __align__(16) float g_part[(size_t)SPLITK * KBOX * CCH];   // 16.8 MB

// ---- f32x2 packed-FMA helpers (numerically validated vs scalar SGEMM) ----
__device__ __forceinline__ ull dup2(float v) {
    ull d; asm("mov.b64 %0, {%1, %1};" : "=l"(d) : "f"(v)); return d;
}
__device__ __forceinline__ ull fma2(ull a, ull b, ull c) {
    ull d; asm("fma.rn.f32x2 %0, %1, %2, %3;" : "=l"(d) : "l"(a), "l"(b), "l"(c)); return d;
}
__device__ __forceinline__ void unpack2(ull v, float& lo, float& hi) {
    asm("mov.b64 {%0, %1}, %2;" : "=f"(lo), "=f"(hi) : "l"(v));
}

// ============================================================================
// Stage 1: ROI max pool (R13-proven bin math; ILP restructure).
// 256 threads/block (R15 used 512 -> reg-file overflow at launch: 49-reg
// accumulator x 512 thr > 64K regs/block). Grid (KBOX, 2): blockIdx.y picks
// the channel half. Stream ROI rows once; 7 independent column-bin chains,
// folded into a 7x7 register accumulator with unrolled predicated max.
// bin_sz = roi * rn(1/7) — matches XLA's reciprocal canonicalization (KEY).
// ============================================================================
__global__ __launch_bounds__(256) void pool_kernel(const float* __restrict__ x,
                                                   const float* __restrict__ boxes) {
    const int k = blockIdx.x;
    const int c = blockIdx.y * 256 + threadIdx.x;

    const int   b  = (int)boxes[k * 5 + 0];
    const float x1 = rintf(boxes[k * 5 + 1] * 32.0f);   // *32 exact (2^5)
    const float y1 = rintf(boxes[k * 5 + 2] * 32.0f);
    const float x2 = rintf(boxes[k * 5 + 3] * 32.0f);
    const float y2 = rintf(boxes[k * 5 + 4] * 32.0f);
    const float rw = fmaxf(x2 - x1 + 1.0f, 1.0f);
    const float rh = fmaxf(y2 - y1 + 1.0f, 1.0f);
    const float bw = __fmul_rn(rw, RECIP7);   // reciprocal-multiply, like XLA
    const float bh = __fmul_rn(rh, RECIP7);

    int xlo[OSZ], xhi[OSZ], ylo[OSZ], yhi[OSZ];
#pragma unroll
    for (int p = 0; p < OSZ; p++) {
        float pf = (float)p;
        float lo = floorf(__fmul_rn(pf, bw)) + x1;
        float hi = ceilf(__fmul_rn(pf + 1.0f, bw)) + x1;
        lo = fminf(fmaxf(lo, 0.0f), 32.0f);
        hi = fminf(fmaxf(hi, 0.0f), 32.0f);
        xlo[p] = (int)lo; xhi[p] = (int)hi;
        lo = floorf(__fmul_rn(pf, bh)) + y1;
        hi = ceilf(__fmul_rn(pf + 1.0f, bh)) + y1;
        lo = fminf(fmaxf(lo, 0.0f), 32.0f);
        hi = fminf(fmaxf(hi, 0.0f), 32.0f);
        ylo[p] = (int)lo; yhi[p] = (int)hi;
    }

    // feat[b,c,h,w] = x[b, h*32+w, c]
    const float* xb = x + (size_t)b * NTOK * CCH + c;

    float pool[OSZ][OSZ];
#pragma unroll
    for (int i = 0; i < OSZ; i++)
#pragma unroll
        for (int j = 0; j < OSZ; j++) pool[i][j] = NEGINF;

    const int hmin = ylo[0], hmax = yhi[OSZ - 1];   // lo/hi are monotone
    for (int h = hmin; h < hmax; h++) {
        const float* row = xb + (size_t)(h * HH) * CCH;
        float cm[OSZ];
#pragma unroll
        for (int j = 0; j < OSZ; j++) {
            float m = NEGINF;
            for (int w = xlo[j]; w < xhi[j]; w++)
                m = fmaxf(m, row[(size_t)w * CCH]);
            cm[j] = m;
        }
#pragma unroll
        for (int i = 0; i < OSZ; i++) {
            if (h >= ylo[i] && h < yhi[i]) {
#pragma unroll
                for (int j = 0; j < OSZ; j++)
                    pool[i][j] = fmaxf(pool[i][j], cm[j]);
            }
        }
    }

    float* outp = g_pool + (size_t)k * KDIM + (size_t)c * (OSZ * OSZ);
#pragma unroll
    for (int i = 0; i < OSZ; i++)
#pragma unroll
        for (int j = 0; j < OSZ; j++) {
            float v = pool[i][j];
            // empty bin (never touched) stays NEGINF -> 0, same as reference
            outp[i * OSZ + j] = (v <= NEGINF * 0.5f) ? 0.0f : v;
        }
}

// ============================================================================
// Stage 2: split-K GEMM  part[s] = pool(256 x Ks) * conv_w^T(Ks x 512)
// 128x128x8 tiles, 256 threads, 8x8 micro-tile (32 FFMA2 / 6 LDS.128 per kk),
// double-buffered smem + register prefetch (1 sync per K-step).
// ============================================================================
__global__ __launch_bounds__(256, 2) void gemm_kernel(const float* __restrict__ conv_w) {
    __shared__ __align__(16) ull   As2[2][BK][BM + 2];   // dup (a,a); row 1040B
    __shared__ __align__(16) float Bs[2][BK][BN + 4];    // row 528B

    const int tid  = threadIdx.x;
    const int n0   = blockIdx.x * BN;
    const int m0   = blockIdx.y * BM;
    const int kbeg = blockIdx.z * KSPLIT;

    const int lrow = tid >> 1;          // 0..127
    const int lk4  = (tid & 1) * 4;     // 0,4
    const int ty8  = (tid >> 4) * 8;    // 0..120
    const int tx8  = (tid & 15) * 8;    // 0..120

    const float* Ag = g_pool + (size_t)(m0 + lrow) * KDIM + kbeg + lk4;
    const float* Bg = conv_w + (size_t)(n0 + lrow) * KDIM + kbeg + lk4;

    ull acc[8][4];
#pragma unroll
    for (int r = 0; r < 8; r++)
#pragma unroll
        for (int q = 0; q < 4; q++) acc[r][q] = 0ull;

    // prefetch kt=0
    float4 av = *(const float4*)Ag;
    float4 bv = *(const float4*)Bg;

    int p = 0;
    for (int kt = 0; kt < KITER; kt++) {
        As2[p][lk4 + 0][lrow] = dup2(av.x);
        As2[p][lk4 + 1][lrow] = dup2(av.y);
        As2[p][lk4 + 2][lrow] = dup2(av.z);
        As2[p][lk4 + 3][lrow] = dup2(av.w);
        Bs[p][lk4 + 0][lrow] = bv.x;
        Bs[p][lk4 + 1][lrow] = bv.y;
        Bs[p][lk4 + 2][lrow] = bv.z;
        Bs[p][lk4 + 3][lrow] = bv.w;
        __syncthreads();

        if (kt + 1 < KITER) {            // prefetch next K-step (LDG hidden)
            Ag += BK; Bg += BK;
            av = *(const float4*)Ag;
            bv = *(const float4*)Bg;
        }

#pragma unroll
        for (int kk = 0; kk < BK; kk++) {
            const ulonglong2 a01 = *(const ulonglong2*)&As2[p][kk][ty8];
            const ulonglong2 a23 = *(const ulonglong2*)&As2[p][kk][ty8 + 2];
            const ulonglong2 a45 = *(const ulonglong2*)&As2[p][kk][ty8 + 4];
            const ulonglong2 a67 = *(const ulonglong2*)&As2[p][kk][ty8 + 6];
            const ulonglong2 b01 = *(const ulonglong2*)&Bs[p][kk][tx8];
            const ulonglong2 b23 = *(const ulonglong2*)&Bs[p][kk][tx8 + 4];
            const ull a[8] = {a01.x, a01.y, a23.x, a23.y, a45.x, a45.y, a67.x, a67.y};
            const ull bb[4] = {b01.x, b01.y, b23.x, b23.y};
#pragma unroll
            for (int r = 0; r < 8; r++)
#pragma unroll
                for (int q = 0; q < 4; q++)
                    acc[r][q] = fma2(a[r], bb[q], acc[r][q]);
        }
        p ^= 1;
    }

    float* P = g_part + (size_t)blockIdx.z * KBOX * CCH;
#pragma unroll
    for (int r = 0; r < 8; r++) {
        float4 v0, v1;
        unpack2(acc[r][0], v0.x, v0.y);
        unpack2(acc[r][1], v0.z, v0.w);
        unpack2(acc[r][2], v1.x, v1.y);
        unpack2(acc[r][3], v1.z, v1.w);
        float* dst = &P[(size_t)(m0 + ty8 + r) * CCH + n0 + tx8];
        *(float4*)dst       = v0;
        *(float4*)(dst + 4) = v1;
    }
}

// ============================================================================
// Stage 3: reduce split-K partials + bias -> out (256 x 512), deterministic.
// ============================================================================
__global__ __launch_bounds__(256) void reduce_kernel(const float* __restrict__ bias,
                                                     float* __restrict__ out) {
    const int idx = blockIdx.x * blockDim.x + threadIdx.x;
    if (idx >= KBOX * CCH) return;
    float sum = bias[idx & (CCH - 1)];
#pragma unroll
    for (int p = 0; p < SPLITK; p++)
        sum += g_part[(size_t)p * KBOX * CCH + idx];
    out[idx] = sum;
}

extern "C" void kernel_launch(void* const* d_in, const int* in_sizes, int n_in,
                              void* d_out, int out_size) {
    // Select inputs by element count (robust to metadata ordering):
    // x=4194304, boxes=1280, box_labels=256, conv_w=12845056, conv_b=512
    const float* x      = nullptr;
    const float* boxes  = nullptr;
    const float* conv_w = nullptr;
    const float* conv_b = nullptr;
    for (int i = 0; i < n_in; i++) {
        switch (in_sizes[i]) {
            case 4194304:  x      = (const float*)d_in[i]; break;
            case 1280:     boxes  = (const float*)d_in[i]; break;
            case 12845056: conv_w = (const float*)d_in[i]; break;
            case 512:      conv_b = (const float*)d_in[i]; break;
            default: break;                    // box_labels (256): unused
        }
    }
    float* out = (float*)d_out;
    const size_t NX = 4194304;

    // Output layout: (x passthrough, box_feats)
    cudaMemcpyAsync(out, x, NX * sizeof(float), cudaMemcpyDeviceToDevice, 0);

    dim3 pgrid(KBOX, 2);                      // 256 thr/block, 2 channel halves
    pool_kernel<<<pgrid, 256>>>(x, boxes);

    dim3 grid(CCH / BN, KBOX / BM, SPLITK);   // (4, 2, 32) = 256 CTAs
    gemm_kernel<<<grid, 256>>>(conv_w);

    reduce_kernel<<<(KBOX * CCH + 255) / 256, 256>>>(conv_b, out + NX);
}